// round 5
// baseline (speedup 1.0000x reference)
#include <cuda_runtime.h>
#include <math.h>

// Problem constants (match reference)
#define T_STEPS 1024
#define B_SIZE  32768
#define G1      50
#define H1      32
#define G2      20
#define CHUNK   64
#define NCHUNK  (T_STEPS / CHUNK)       // 16
#define NPAIR   (B_SIZE / 2)            // 16384

// Device-global scratch (no allocation allowed)
__device__ float  g_cbeta[T_STEPS];
__device__ float4 g_snap[NCHUNK * NPAIR];   // (I,S) pairs, 4 MB

// ---------------------------------------------------------------------------
// Kernel 1: cbeta[t] = dt * softplus(KAN2(KAN1(t/T))) — one block per t.
// ---------------------------------------------------------------------------
__global__ void kan_beta_kernel(const float* __restrict__ t_steps,
                                const float* __restrict__ grid1,
                                const float* __restrict__ spline_w1, // [50,32]
                                const float* __restrict__ base_w1,   // [32]
                                const float* __restrict__ grid2,
                                const float* __restrict__ spline_w2, // [640]
                                const float* __restrict__ base_w2)   // [32]
{
    __shared__ float basis1[G1];
    __shared__ float hsm[H1];
    __shared__ float warpsum[2];

    const int t   = blockIdx.x;
    const int tid = threadIdx.x;
    const float x = t_steps[t];

    if (tid < G1) {
        float d = x - grid1[tid];
        basis1[tid] = __expf(-10.0f * d * d);
    }
    __syncthreads();

    if (tid < H1) {
        float acc = x * base_w1[tid];
        #pragma unroll
        for (int g = 0; g < G1; g++)
            acc = fmaf(basis1[g], spline_w1[g * H1 + tid], acc);
        hsm[tid] = acc;
    }
    __syncthreads();

    float acc = 0.0f;
    #pragma unroll
    for (int k = 0; k < (H1 * G2) / 64; k++) {   // 10
        int idx = tid + k * 64;
        int i = idx / G2;
        int g = idx - i * G2;
        float d = hsm[i] - grid2[g];
        acc = fmaf(__expf(-10.0f * d * d), spline_w2[idx], acc);
    }
    if (tid < H1) acc = fmaf(hsm[tid], base_w2[tid], acc);

    #pragma unroll
    for (int o = 16; o > 0; o >>= 1)
        acc += __shfl_down_sync(0xFFFFFFFFu, acc, o);
    if ((tid & 31) == 0) warpsum[tid >> 5] = acc;
    __syncthreads();
    if (tid == 0) {
        float v = warpsum[0] + warpsum[1];
        float beta = fmaxf(v, 0.0f) + log1pf(expf(-fabsf(v)));  // stable softplus
        float dt = t_steps[1] - t_steps[0];
        g_cbeta[t] = dt * beta;
    }
}

// ---------------------------------------------------------------------------
// Kernel A: full scan, NO output stores — only (I,S) snapshots every CHUNK
// steps. One thread per batch element; minimal dependent chain (~12 cyc/iter).
// Clips removed: gamma=softplus(5), beta>=0 keep state in [0,1] so the
// fminf/fmaxf(0,5) are exact identities (verified bit-stable in R4).
// ---------------------------------------------------------------------------
__global__ void __launch_bounds__(64)
scan_snap_kernel(const float* __restrict__ initial_I,
                 const float* __restrict__ t_steps,
                 const float* __restrict__ gamma_param)
{
    __shared__ float scb[T_STEPS];
    #pragma unroll
    for (int i = 0; i < T_STEPS / 64; i++)
        scb[threadIdx.x + i * 64] = g_cbeta[threadIdx.x + i * 64];

    const int b = blockIdx.x * 64 + threadIdx.x;
    float I = initial_I[b];
    float S = 1.0f - I;

    const float gp    = gamma_param[0];
    const float gamma = fmaxf(gp, 0.0f) + log1pf(expf(-fabsf(gp)));
    const float dt    = t_steps[1] - t_steps[0];
    const float a     = 1.0f - dt * gamma;

    __syncthreads();

    float2* snap2 = (float2*)g_snap;
    #pragma unroll 1
    for (int c = 0; c < NCHUNK; c++) {
        float2 sv; sv.x = I; sv.y = S;
        snap2[c * B_SIZE + b] = sv;          // state BEFORE step c*CHUNK
        #pragma unroll
        for (int u = 0; u < CHUNK; u++) {
            const float cb = scb[c * CHUNK + u];
            const float ni = cb * (S * I);
            I = fmaf(I, a, ni);
            S = S - ni;
        }
    }
}

// ---------------------------------------------------------------------------
// Kernel B: high-occupancy replay + store. 16 chunks x 16384 pairs.
// Each thread: load snapshot (2 elems), replay 64 steps (bit-identical to
// kernel A's trajectory), store float2 per step. 262144 threads -> ~85% occ.
// ---------------------------------------------------------------------------
__global__ void __launch_bounds__(256)
store_kernel(const float* __restrict__ t_steps,
             const float* __restrict__ gamma_param,
             float* __restrict__ out)
{
    const int c  = blockIdx.x >> 6;          // 64 blocks per chunk
    const int pb = blockIdx.x & 63;

    __shared__ float scb[CHUNK];
    if (threadIdx.x < CHUNK)
        scb[threadIdx.x] = g_cbeta[c * CHUNK + threadIdx.x];
    __syncthreads();

    const int p = pb * 256 + threadIdx.x;    // pair index 0..16383

    const float4 s = g_snap[c * NPAIR + p];
    float I0 = s.x, S0 = s.y, I1 = s.z, S1 = s.w;

    const float gp    = gamma_param[0];
    const float gamma = fmaxf(gp, 0.0f) + log1pf(expf(-fabsf(gp)));
    const float dt    = t_steps[1] - t_steps[0];
    const float a     = 1.0f - dt * gamma;

    float2* outp = ((float2*)out) + (size_t)c * CHUNK * NPAIR + p;
    #pragma unroll 8
    for (int u = 0; u < CHUNK; u++) {
        const float cb  = scb[u];
        const float ni0 = cb * (S0 * I0);
        const float ni1 = cb * (S1 * I1);
        I0 = fmaf(I0, a, ni0);
        I1 = fmaf(I1, a, ni1);
        S0 = S0 - ni0;
        S1 = S1 - ni1;
        float2 v; v.x = I0; v.y = I1;
        outp[(size_t)u * NPAIR] = v;
    }
}

// ---------------------------------------------------------------------------
// Inputs (metadata order):
// 0: t_steps [1024], 1: initial_I [32768], 2: grid1 [50], 3: spline_w1 [1600],
// 4: base_w1 [32], 5: grid2 [20], 6: spline_w2 [640], 7: base_w2 [32],
// 8: gamma_param [1]
// ---------------------------------------------------------------------------
extern "C" void kernel_launch(void* const* d_in, const int* in_sizes, int n_in,
                              void* d_out, int out_size)
{
    const float* t_steps    = (const float*)d_in[0];
    const float* initial_I  = (const float*)d_in[1];
    const float* grid1      = (const float*)d_in[2];
    const float* spline_w1  = (const float*)d_in[3];
    const float* base_w1    = (const float*)d_in[4];
    const float* grid2      = (const float*)d_in[5];
    const float* spline_w2  = (const float*)d_in[6];
    const float* base_w2    = (const float*)d_in[7];
    const float* gamma_p    = (const float*)d_in[8];
    float* out              = (float*)d_out;

    kan_beta_kernel<<<T_STEPS, 64>>>(t_steps, grid1, spline_w1, base_w1,
                                     grid2, spline_w2, base_w2);
    scan_snap_kernel<<<B_SIZE / 64, 64>>>(initial_I, t_steps, gamma_p);
    store_kernel<<<NCHUNK * 64, 256>>>(t_steps, gamma_p, out);
}

// round 6
// speedup vs baseline: 1.2914x; 1.2914x over previous
#include <cuda_runtime.h>
#include <math.h>

// Problem constants (match reference)
#define T_STEPS 1024
#define B_SIZE  32768
#define G1      50
#define H1      32
#define G2      20

// Scratch: dt * beta[t] (device global — no allocation allowed)
__device__ float g_cbeta[T_STEPS];

// ---------------------------------------------------------------------------
// Kernel 1: cbeta[t] = dt * softplus(KAN2(KAN1(t/T))) — one block per t.
// Layer-2 RBF factorized: exp(-10(h-g)^2) = e0 * tk * C2[k] with tk a
// geometric running product -> 3 exps per (t,i) instead of 20.
// MUFU count per t: 50 (layer1) + 20 (C2 table) + 96 (layer2) ~ 170.
// ---------------------------------------------------------------------------
__global__ void kan_beta_kernel(const float* __restrict__ t_steps,
                                const float* __restrict__ grid1,
                                const float* __restrict__ spline_w1, // [50,32]
                                const float* __restrict__ base_w1,   // [32]
                                const float* __restrict__ grid2,
                                const float* __restrict__ spline_w2, // [32,20]
                                const float* __restrict__ base_w2)   // [32]
{
    __shared__ float basis1[G1];
    __shared__ float hsm[H1];
    __shared__ float C2[G2];

    const int t   = blockIdx.x;
    const int tid = threadIdx.x;
    const float x = t_steps[t];

    // Layer-1 RBF basis (50 direct exps; x in [0,1), always in range)
    if (tid < G1) {
        float d = x - grid1[tid];
        basis1[tid] = __expf(-10.0f * d * d);
    }
    // C2[k] = exp(-10*(grid2[k]-0.5)^2)  (threads 44..63; 44..49 do both)
    if (tid >= 44) {
        int k = tid - 44;
        float v = grid2[k] - 0.5f;
        C2[k] = __expf(-10.0f * v * v);
    }
    __syncthreads();

    // h[j] = x*base_w1[j] + sum_g basis1[g]*spline_w1[g*32+j]
    if (tid < H1) {
        float acc = x * base_w1[tid];
        #pragma unroll
        for (int g = 0; g < G1; g++)
            acc = fmaf(basis1[g], spline_w1[g * H1 + tid], acc);
        hsm[tid] = acc;
    }
    __syncthreads();

    // Layer 2 (warp 0 only): i = tid
    if (tid < H1) {
        const float h  = hsm[tid];
        float u = h - 0.5f;
        u = fminf(fmaxf(u, -2.5f), 2.5f);   // where clamp binds, basis ~ 0 anyway
        const float v0 = grid2[0] - 0.5f;
        const float dv = grid2[1] - grid2[0];
        const float e0 = __expf(-10.0f * u * u);
        float       tk = __expf(20.0f * u * v0);
        const float f  = __expf(20.0f * u * dv);

        float acc = 0.0f;
        #pragma unroll
        for (int k = 0; k < G2; k++) {
            acc = fmaf(tk * C2[k], spline_w2[tid * G2 + k], acc);
            tk *= f;
        }
        acc = fmaf(h, base_w2[tid], e0 * acc);

        // warp reduce 32 -> 1
        #pragma unroll
        for (int o = 16; o > 0; o >>= 1)
            acc += __shfl_down_sync(0xFFFFFFFFu, acc, o);

        if (tid == 0) {
            float beta = fmaxf(acc, 0.0f) + log1pf(expf(-fabsf(acc)));  // softplus
            float dt = t_steps[1] - t_steps[0];
            g_cbeta[t] = dt * beta;
        }
    }
}

// ---------------------------------------------------------------------------
// Kernel 2: Euler SIR scan — one thread per batch element (R3 config: best
// measured). Clips removed (state provably stays in [0,1]; bit-identical,
// verified R4). __stcs streaming stores hint evict-first in L2.
// ---------------------------------------------------------------------------
__global__ void __launch_bounds__(64)
sir_scan_kernel(const float* __restrict__ initial_I,
                const float* __restrict__ t_steps,
                const float* __restrict__ gamma_param,
                float* __restrict__ out)
{
    __shared__ float scb[T_STEPS + 8];   // padded: t+1 prefetch never guards
    #pragma unroll
    for (int i = 0; i < T_STEPS / 64; i++)
        scb[threadIdx.x + i * 64] = g_cbeta[threadIdx.x + i * 64];
    if (threadIdx.x < 8) scb[T_STEPS + threadIdx.x] = 0.0f;

    const int b = blockIdx.x * 64 + threadIdx.x;

    float I = initial_I[b];
    float S = 1.0f - I;

    const float gp    = gamma_param[0];
    const float gamma = fmaxf(gp, 0.0f) + log1pf(expf(-fabsf(gp)));
    const float dt    = t_steps[1] - t_steps[0];
    const float a     = 1.0f - dt * gamma;   // I' = I*a + ni

    __syncthreads();

    float* outp = out + b;
    float cb = scb[0];
    #pragma unroll 8
    for (int t = 0; t < T_STEPS; t++) {
        const float cb_n = scb[t + 1];       // prefetch next beta
        const float ni = cb * (S * I);       // dt * new_infections
        I = fmaf(I, a, ni);
        S = S - ni;
        __stcs(outp + (size_t)t * B_SIZE, I);
        cb = cb_n;
    }
}

// ---------------------------------------------------------------------------
// Inputs (metadata order):
// 0: t_steps [1024], 1: initial_I [32768], 2: grid1 [50], 3: spline_w1 [1600],
// 4: base_w1 [32], 5: grid2 [20], 6: spline_w2 [640], 7: base_w2 [32],
// 8: gamma_param [1]
// ---------------------------------------------------------------------------
extern "C" void kernel_launch(void* const* d_in, const int* in_sizes, int n_in,
                              void* d_out, int out_size)
{
    const float* t_steps    = (const float*)d_in[0];
    const float* initial_I  = (const float*)d_in[1];
    const float* grid1      = (const float*)d_in[2];
    const float* spline_w1  = (const float*)d_in[3];
    const float* base_w1    = (const float*)d_in[4];
    const float* grid2      = (const float*)d_in[5];
    const float* spline_w2  = (const float*)d_in[6];
    const float* base_w2    = (const float*)d_in[7];
    const float* gamma_p    = (const float*)d_in[8];
    float* out              = (float*)d_out;

    kan_beta_kernel<<<T_STEPS, 64>>>(t_steps, grid1, spline_w1, base_w1,
                                     grid2, spline_w2, base_w2);
    sir_scan_kernel<<<B_SIZE / 64, 64>>>(initial_I, t_steps, gamma_p, out);
}